// round 4
// baseline (speedup 1.0000x reference)
#include <cuda_runtime.h>
#include <cuda_bf16.h>
#include <cstdint>

#define S     2048
#define HID   2048
#define NH    32
#define NKV   8
#define HD    64
#define KVDIM (NKV*HD)   // 512
#define CTX   (S-10)     // 2038: rows >= CTX use narrow rope

typedef unsigned long long ull;

// ---------------- packed f32x2 helpers ----------------
__device__ __forceinline__ ull dup2(float x) {
    ull r; asm("mov.b64 %0, {%1, %1};" : "=l"(r) : "f"(x)); return r;
}
__device__ __forceinline__ void ffma2(ull& c, ull a, ull b) {
    asm("fma.rn.f32x2 %0, %1, %2, %0;" : "+l"(c) : "l"(a), "l"(b));
}
__device__ __forceinline__ void fmul2(ull& c, ull a) {
    asm("mul.rn.f32x2 %0, %0, %1;" : "+l"(c) : "l"(a));
}
__device__ __forceinline__ float2 unpack2(ull v) {
    float lo, hi; asm("mov.b64 {%0, %1}, %2;" : "=f"(lo), "=f"(hi) : "l"(v));
    return make_float2(lo, hi);
}
__device__ __forceinline__ uint32_t smem_u32(const void* p) {
    uint32_t a;
    asm("{ .reg .u64 t; cvta.to.shared.u64 t, %1; cvt.u32.u64 %0, t; }" : "=r"(a) : "l"(p));
    return a;
}
__device__ __forceinline__ void lds2u64(uint32_t a, ull& x, ull& y) {
    asm volatile("ld.shared.v2.b64 {%0,%1}, [%2];" : "=l"(x), "=l"(y) : "r"(a));
}

// FMA-pipe 2^t (t <= 0 expected; clamped). Accuracy ~3e-6 rel. No MUFU.
__device__ __forceinline__ float fexp2(float t) {
    t = fmaxf(t, -126.0f);
    float r = t + 12582912.0f;            // round-to-nearest integer (magic)
    float f = t - (r - 12582912.0f);      // frac in [-0.5, 0.5]
    float p = 1.3333558146428443e-3f;
    p = fmaf(p, f, 9.6181291976354e-3f);
    p = fmaf(p, f, 5.550410866482158e-2f);
    p = fmaf(p, f, 2.402265069591007e-1f);
    p = fmaf(p, f, 6.931471805599453e-1f);
    p = fmaf(p, f, 1.0f);
    return __int_as_float(__float_as_int(p) + (__float_as_int(r) << 23));
}

// ---------------- mma.sync primitives (compute_103-safe) ----------------
__device__ __forceinline__ void cp16(uint32_t s, const void* g) {
    asm volatile("cp.async.cg.shared.global [%0], [%1], 16;" :: "r"(s), "l"(g));
}
#define CP_COMMIT() asm volatile("cp.async.commit_group;" ::: "memory")
#define CP_WAIT1()  asm volatile("cp.async.wait_group 1;" ::: "memory")

__device__ __forceinline__ void ldsm_x4(uint32_t addr, uint32_t& r0, uint32_t& r1,
                                        uint32_t& r2, uint32_t& r3) {
    asm volatile("ldmatrix.sync.aligned.m8n8.x4.shared.b16 {%0,%1,%2,%3}, [%4];"
                 : "=r"(r0), "=r"(r1), "=r"(r2), "=r"(r3) : "r"(addr));
}
__device__ __forceinline__ void mma16816(float* c, const uint32_t* a, const uint32_t* b) {
    asm volatile(
        "mma.sync.aligned.m16n8k16.row.col.f32.bf16.bf16.f32 "
        "{%0,%1,%2,%3}, {%4,%5,%6,%7}, {%8,%9}, {%0,%1,%2,%3};"
        : "+f"(c[0]), "+f"(c[1]), "+f"(c[2]), "+f"(c[3])
        : "r"(a[0]), "r"(a[1]), "r"(a[2]), "r"(a[3]), "r"(b[0]), "r"(b[1]));
}

// ---------------- scratch (static device globals; no allocs) ----------------
__device__ float g_Q   [S*HID];
__device__ float g_K   [S*KVDIM];
__device__ float g_V   [S*KVDIM];
__device__ float g_Qr  [S*HID];
__device__ float g_bK  [S*KVDIM];
__device__ float g_nK  [S*KVDIM];
__device__ float g_attn[S*HID];
__device__ __nv_bfloat16 g_hH[S*HID],     g_hL[S*HID];
__device__ __nv_bfloat16 g_WqH[HID*HID],  g_WqL[HID*HID];
__device__ __nv_bfloat16 g_WkH[KVDIM*HID],g_WkL[KVDIM*HID];
__device__ __nv_bfloat16 g_WvH[KVDIM*HID],g_WvL[KVDIM*HID];
__device__ __nv_bfloat16 g_WoH[HID*HID],  g_WoL[HID*HID];
__device__ __nv_bfloat16 g_aH[S*HID],     g_aL[S*HID];

// ---------------- fp32 -> bf16 hi/lo split ----------------
__global__ __launch_bounds__(256)
void split4_kernel(const float* __restrict__ x, __nv_bfloat16* __restrict__ hi,
                   __nv_bfloat16* __restrict__ lo, int n4)
{
    int i = blockIdx.x * 256 + threadIdx.x;
    if (i >= n4) return;
    float4 v = ((const float4*)x)[i];
    __nv_bfloat16 h0 = __float2bfloat16(v.x);
    __nv_bfloat16 h1 = __float2bfloat16(v.y);
    __nv_bfloat16 h2 = __float2bfloat16(v.z);
    __nv_bfloat16 h3 = __float2bfloat16(v.w);
    __nv_bfloat162 H0 = __nv_bfloat162(h0, h1), H1 = __nv_bfloat162(h2, h3);
    __nv_bfloat162 L0 = __nv_bfloat162(__float2bfloat16(v.x - __bfloat162float(h0)),
                                       __float2bfloat16(v.y - __bfloat162float(h1)));
    __nv_bfloat162 L1 = __nv_bfloat162(__float2bfloat16(v.z - __bfloat162float(h2)),
                                       __float2bfloat16(v.w - __bfloat162float(h3)));
    ((__nv_bfloat162*)hi)[i*2+0] = H0; ((__nv_bfloat162*)hi)[i*2+1] = H1;
    ((__nv_bfloat162*)lo)[i*2+0] = L0; ((__nv_bfloat162*)lo)[i*2+1] = L1;
}

// ---------------- mma.sync split-bf16 GEMM: C[M,N] = A[M,K] @ B[N,K]^T -----
#define STG      16384
#define SM_STAGE (4*STG)          // 64 KB
#define SM_TOTAL (2*SM_STAGE)     // 128 KB

__device__ __forceinline__ void load_stage(
    uint32_t sbuf,
    const __nv_bfloat16* __restrict__ Ah, const __nv_bfloat16* __restrict__ Al,
    const __nv_bfloat16* __restrict__ Bh, const __nv_bfloat16* __restrict__ Bl,
    int mBase, int nBase, int Kdim, int k0, int tid)
{
#pragma unroll
    for (int i = 0; i < 4; i++) {
        int u = i * 256 + tid;
        int r = u >> 3, c = u & 7;
        uint32_t so = (uint32_t)(r * 128 + ((c ^ (r & 7)) << 4));
        size_t eoffA = (size_t)(mBase + r) * Kdim + k0 + c * 8;
        size_t eoffB = (size_t)(nBase + r) * Kdim + k0 + c * 8;
        cp16(sbuf +          so, Ah + eoffA);
        cp16(sbuf +   STG  + so, Al + eoffA);
        cp16(sbuf + 2*STG  + so, Bh + eoffB);
        cp16(sbuf + 3*STG  + so, Bl + eoffB);
    }
}

__global__ __launch_bounds__(256)
void mma_gemm(const __nv_bfloat16* __restrict__ Ah, const __nv_bfloat16* __restrict__ Al,
              const __nv_bfloat16* __restrict__ Bh, const __nv_bfloat16* __restrict__ Bl,
              float* __restrict__ C, int Ntot, int Kdim)
{
    extern __shared__ char dyns[];
    const uint32_t sb = smem_u32(dyns);

    const int tid  = threadIdx.x;
    const int lane = tid & 31;
    const int wid  = tid >> 5;
    const int wm   = wid & 1;
    const int wn   = wid >> 1;
    const int mBase = blockIdx.y * 128, nBase = blockIdx.x * 128;

    float acc[4][4][4];
#pragma unroll
    for (int i = 0; i < 4; i++)
#pragma unroll
        for (int j = 0; j < 4; j++)
#pragma unroll
            for (int k = 0; k < 4; k++) acc[i][j][k] = 0.0f;

    const int NC = Kdim >> 6;

    load_stage(sb,            Ah, Al, Bh, Bl, mBase, nBase, Kdim, 0,  tid);
    CP_COMMIT();
    load_stage(sb + SM_STAGE, Ah, Al, Bh, Bl, mBase, nBase, Kdim, 64, tid);
    CP_COMMIT();

    const int aRow = wm * 64;
    const int bRow = wn * 32;

    for (int c = 0; c < NC; c++) {
        CP_WAIT1();
        __syncthreads();
        const uint32_t sbuf = sb + (c & 1) * SM_STAGE;
        const uint32_t sAh = sbuf, sAl = sbuf + STG, sBh = sbuf + 2*STG, sBl = sbuf + 3*STG;

#pragma unroll
        for (int ks = 0; ks < 4; ks++) {
            uint32_t aH[4][4], aL[4][4], bH[4][2], bL[4][2];
            {
                int rA = aRow + (lane & 15);
                int ccA = ks * 2 + (lane >> 4);
#pragma unroll
                for (int mf = 0; mf < 4; mf++) {
                    int r = rA + mf * 16;
                    uint32_t so = (uint32_t)(r * 128 + ((ccA ^ (r & 7)) << 4));
                    ldsm_x4(sAh + so, aH[mf][0], aH[mf][1], aH[mf][2], aH[mf][3]);
                    ldsm_x4(sAl + so, aL[mf][0], aL[mf][1], aL[mf][2], aL[mf][3]);
                }
            }
            {
                int rB0 = bRow + (lane & 7) + ((lane >> 4) << 3);
                int ccB = ks * 2 + ((lane >> 3) & 1);
#pragma unroll
                for (int nf2 = 0; nf2 < 2; nf2++) {
                    int r = rB0 + nf2 * 16;
                    uint32_t so = (uint32_t)(r * 128 + ((ccB ^ (r & 7)) << 4));
                    ldsm_x4(sBh + so, bH[nf2*2][0], bH[nf2*2][1], bH[nf2*2+1][0], bH[nf2*2+1][1]);
                    ldsm_x4(sBl + so, bL[nf2*2][0], bL[nf2*2][1], bL[nf2*2+1][0], bL[nf2*2+1][1]);
                }
            }
#pragma unroll
            for (int mf = 0; mf < 4; mf++)
#pragma unroll
                for (int nf = 0; nf < 4; nf++) {
                    mma16816(acc[mf][nf], aH[mf], bH[nf]);
                    mma16816(acc[mf][nf], aL[mf], bH[nf]);
                    mma16816(acc[mf][nf], aH[mf], bL[nf]);
                }
        }
        __syncthreads();
        if (c + 2 < NC)
            load_stage(sb + (c & 1) * SM_STAGE, Ah, Al, Bh, Bl,
                       mBase, nBase, Kdim, (c + 2) * 64, tid);
        CP_COMMIT();
    }

#pragma unroll
    for (int mf = 0; mf < 4; mf++) {
        int row0 = mBase + wm * 64 + mf * 16 + (lane >> 2);
#pragma unroll
        for (int nf = 0; nf < 4; nf++) {
            int col = nBase + wn * 32 + nf * 8 + (lane & 3) * 2;
            *(float2*)&C[(size_t)row0 * Ntot + col]       = make_float2(acc[mf][nf][0], acc[mf][nf][1]);
            *(float2*)&C[(size_t)(row0 + 8) * Ntot + col] = make_float2(acc[mf][nf][2], acc[mf][nf][3]);
        }
    }
}

// ---------------- RoPE: Qr (per-row variant), bK, nK --------------------
__global__ void rope_kernel(const float* __restrict__ Q, const float* __restrict__ K,
                            float* __restrict__ Qr, float* __restrict__ bK,
                            float* __restrict__ nK)
{
    const int s = blockIdx.x;
    const int tid = threadIdx.x; // 256
    const bool narrowRow = (s >= CTX);

    __shared__ float cb[32], sb[32], cn[32], sn[32];
    if (tid < 32) {
        double inv = pow(10000.0, -(double)tid / 32.0);
        double ab = (double)s * inv;
        double an = ((double)s * 0.25) * inv;
        cb[tid] = (float)cos(ab); sb[tid] = (float)sin(ab);
        cn[tid] = (float)cos(an); sn[tid] = (float)sin(an);
    }
    __syncthreads();

    for (int p = tid; p < NH * 32; p += 256) {
        int h = p >> 5, d = p & 31;
        size_t base = (size_t)s * HID + h * HD;
        float x1 = Q[base + d];
        float x2 = Q[base + d + 32];
        float c  = narrowRow ? cn[d] : cb[d];
        float si = narrowRow ? sn[d] : sb[d];
        Qr[base + d]      = x1 * c - x2 * si;
        Qr[base + d + 32] = x2 * c + x1 * si;
    }
    for (int p = tid; p < NKV * 32; p += 256) {
        int h = p >> 5, d = p & 31;
        size_t base = (size_t)s * KVDIM + h * HD;
        float x1 = K[base + d];
        float x2 = K[base + d + 32];
        bK[base + d]      = x1 * cb[d] - x2 * sb[d];
        bK[base + d + 32] = x2 * cb[d] + x1 * sb[d];
        nK[base + d]      = x1 * cn[d] - x2 * sn[d];
        nK[base + d + 32] = x2 * cn[d] + x1 * sn[d];
    }
}

// ---------------- Flash attention (causal, per-row rope variant) ----------
// 1 query row per thread. Base-2 online softmax, FMA-pipe exp2, v2.b64 smem
// loads, 4-way split dot accumulators. Scale log2(e)/8 folded into Q.
__global__ __launch_bounds__(128)
void flash_kernel(const float* __restrict__ Qr, const float* __restrict__ bK,
                  const float* __restrict__ nK, const float* __restrict__ V,
                  float* __restrict__ attnOut)
{
    __shared__ __align__(16) float Kb_s[64*64];
    __shared__ __align__(16) float Kn_s[64*64];
    __shared__ __align__(16) float Vs  [64*64];

    const int qt  = gridDim.x - 1 - blockIdx.x;   // heavy tiles first
    const int h   = blockIdx.y;
    const int kvh = h >> 2;
    const int tid = threadIdx.x;
    const int row = qt * 128 + tid;
    const bool narrow = (row >= CTX);

    const uint32_t sKb = smem_u32(Kb_s);
    const uint32_t sKn = smem_u32(Kn_s);
    const uint32_t sV  = smem_u32(Vs);

    // Q scaled by log2(e)/sqrt(HD) so scores are already in base-2 units
    const float QSCALE = 1.4426950408889634f * 0.125f;
    ull q2[32];
    {
        const float2* qp = (const float2*)(Qr + (size_t)row * HID + h * HD);
        ull qs = dup2(QSCALE);
#pragma unroll
        for (int i = 0; i < 32; i++) {
            float2 v = qp[i];
            ull t;
            asm("mov.b64 %0, {%1, %2};" : "=l"(t) : "f"(v.x), "f"(v.y));
            fmul2(t, qs);
            q2[i] = t;
        }
    }
    ull o2[32];
#pragma unroll
    for (int i = 0; i < 32; i++) o2[i] = 0ULL;
    float m = -1e30f, l = 0.0f;

    const int nkt = qt * 2 + 2;
    for (int kt = 0; kt < nkt; kt++) {
        if (kt) __syncthreads();
        {
            const float4* src_b = (const float4*)(bK + (size_t)(kt*64) * KVDIM + kvh * HD);
            const float4* src_n = (const float4*)(nK + (size_t)(kt*64) * KVDIM + kvh * HD);
            const float4* src_v = (const float4*)(V  + (size_t)(kt*64) * KVDIM + kvh * HD);
#pragma unroll
            for (int u = tid; u < 1024; u += 128) {
                int jj = u >> 4, d4 = u & 15;
                ((float4*)Kb_s)[jj*16 + d4] = src_b[jj*128 + d4];
                ((float4*)Kn_s)[jj*16 + d4] = src_n[jj*128 + d4];
                ((float4*)Vs  )[jj*16 + d4] = src_v[jj*128 + d4];
            }
        }
        __syncthreads();

        int jmax = row - kt * 64 + 1;
        if (jmax > 64) jmax = 64;
        const uint32_t kbase = narrow ? sKn : sKb;

        for (int jj = 0; jj < jmax; jj++) {
            const uint32_t kr = kbase + jj * 256;
            ull a0 = 0, a1 = 0, a2 = 0, a3 = 0;
#pragma unroll
            for (int i = 0; i < 16; i++) {
                ull k0, k1;
                lds2u64(kr + (i << 4), k0, k1);
                if (i & 1) { ffma2(a2, q2[2*i], k0); ffma2(a3, q2[2*i+1], k1); }
                else       { ffma2(a0, q2[2*i], k0); ffma2(a1, q2[2*i+1], k1); }
            }
            float2 s0 = unpack2(a0), s1 = unpack2(a1), s2 = unpack2(a2), s3 = unpack2(a3);
            float t = (s0.x + s0.y) + (s1.x + s1.y) + ((s2.x + s2.y) + (s3.x + s3.y));

            if (t > m) {
                float csc = fexp2(m - t);
                m = t;
                l *= csc;
                ull c2 = dup2(csc);
#pragma unroll
                for (int i = 0; i < 32; i++) fmul2(o2[i], c2);
            }
            float p = fexp2(t - m);
            l += p;
            ull p2 = dup2(p);
            const uint32_t vr = sV + jj * 256;
#pragma unroll
            for (int i = 0; i < 16; i++) {
                ull v0, v1;
                lds2u64(vr + (i << 4), v0, v1);
                ffma2(o2[2*i],   p2, v0);
                ffma2(o2[2*i+1], p2, v1);
            }
        }
    }

    float invl = 1.0f / l;
    float* op = attnOut + (size_t)row * HID + h * HD;
#pragma unroll
    for (int i = 0; i < 32; i++) {
        float2 v = unpack2(o2[i]);
        ((float2*)op)[i] = make_float2(v.x * invl, v.y * invl);
    }
}

// ---------------- launch ----------------
extern "C" void kernel_launch(void* const* d_in, const int* in_sizes, int n_in,
                              void* d_out, int out_size)
{
    const float* hidden = (const float*)d_in[0];
    const float* Wq = (const float*)d_in[3];
    const float* Wk = (const float*)d_in[4];
    const float* Wv = (const float*)d_in[5];
    const float* Wo = (const float*)d_in[6];
    float* out = (float*)d_out;

    float *qB, *kB, *vB, *qrB, *bkB, *nkB, *atB;
    cudaGetSymbolAddress((void**)&qB,  g_Q);
    cudaGetSymbolAddress((void**)&kB,  g_K);
    cudaGetSymbolAddress((void**)&vB,  g_V);
    cudaGetSymbolAddress((void**)&qrB, g_Qr);
    cudaGetSymbolAddress((void**)&bkB, g_bK);
    cudaGetSymbolAddress((void**)&nkB, g_nK);
    cudaGetSymbolAddress((void**)&atB, g_attn);

    __nv_bfloat16 *hH,*hL,*WqH,*WqL,*WkH,*WkL,*WvH,*WvL,*WoH,*WoL,*aH,*aL;
    cudaGetSymbolAddress((void**)&hH,  g_hH);  cudaGetSymbolAddress((void**)&hL,  g_hL);
    cudaGetSymbolAddress((void**)&WqH, g_WqH); cudaGetSymbolAddress((void**)&WqL, g_WqL);
    cudaGetSymbolAddress((void**)&WkH, g_WkH); cudaGetSymbolAddress((void**)&WkL, g_WkL);
    cudaGetSymbolAddress((void**)&WvH, g_WvH); cudaGetSymbolAddress((void**)&WvL, g_WvL);
    cudaGetSymbolAddress((void**)&WoH, g_WoH); cudaGetSymbolAddress((void**)&WoL, g_WoL);
    cudaGetSymbolAddress((void**)&aH,  g_aH);  cudaGetSymbolAddress((void**)&aL,  g_aL);

    cudaFuncSetAttribute(mma_gemm, cudaFuncAttributeMaxDynamicSharedMemorySize, SM_TOTAL);

    split4_kernel<<<(S*HID/4 + 255)/256, 256>>>(hidden, hH, hL, S*HID/4);
    split4_kernel<<<(HID*HID/4 + 255)/256, 256>>>(Wq, WqH, WqL, HID*HID/4);
    split4_kernel<<<(KVDIM*HID/4 + 255)/256, 256>>>(Wk, WkH, WkL, KVDIM*HID/4);
    split4_kernel<<<(KVDIM*HID/4 + 255)/256, 256>>>(Wv, WvH, WvL, KVDIM*HID/4);
    split4_kernel<<<(HID*HID/4 + 255)/256, 256>>>(Wo, WoH, WoL, HID*HID/4);

    mma_gemm<<<dim3(HID/128,   S/128), 256, SM_TOTAL>>>(hH, hL, WqH, WqL, qB, HID,   HID);
    mma_gemm<<<dim3(KVDIM/128, S/128), 256, SM_TOTAL>>>(hH, hL, WkH, WkL, kB, KVDIM, HID);
    mma_gemm<<<dim3(KVDIM/128, S/128), 256, SM_TOTAL>>>(hH, hL, WvH, WvL, vB, KVDIM, HID);

    rope_kernel<<<S, 256>>>(qB, kB, qrB, bkB, nkB);

    flash_kernel<<<dim3(S/128, NH), 128>>>(qrB, bkB, nkB, vB, atB);

    split4_kernel<<<(S*HID/4 + 255)/256, 256>>>(atB, aH, aL, S*HID/4);
    mma_gemm<<<dim3(HID/128, S/128), 256, SM_TOTAL>>>(aH, aL, WoH, WoL, out, HID, HID);
}

// round 5
// speedup vs baseline: 3.4016x; 3.4016x over previous
#include <cuda_runtime.h>
#include <cuda_bf16.h>
#include <cstdint>

#define S     2048
#define HID   2048
#define NH    32
#define NKV   8
#define HD    64
#define KVDIM (NKV*HD)   // 512
#define CTX   (S-10)     // 2038: rows >= CTX use narrow rope

typedef unsigned long long ull;
typedef __nv_bfloat16 bf16;

__device__ __forceinline__ uint32_t smem_u32(const void* p) {
    uint32_t a;
    asm("{ .reg .u64 t; cvta.to.shared.u64 t, %1; cvt.u32.u64 %0, t; }" : "=r"(a) : "l"(p));
    return a;
}

// ---------------- mma.sync primitives (compute_103-safe) ----------------
__device__ __forceinline__ void cp16(uint32_t s, const void* g) {
    asm volatile("cp.async.cg.shared.global [%0], [%1], 16;" :: "r"(s), "l"(g));
}
#define CP_COMMIT() asm volatile("cp.async.commit_group;" ::: "memory")
#define CP_WAIT1()  asm volatile("cp.async.wait_group 1;" ::: "memory")

__device__ __forceinline__ void ldsm_x4(uint32_t addr, uint32_t& r0, uint32_t& r1,
                                        uint32_t& r2, uint32_t& r3) {
    asm volatile("ldmatrix.sync.aligned.m8n8.x4.shared.b16 {%0,%1,%2,%3}, [%4];"
                 : "=r"(r0), "=r"(r1), "=r"(r2), "=r"(r3) : "r"(addr));
}
__device__ __forceinline__ void ldsm_x4t(uint32_t addr, uint32_t& r0, uint32_t& r1,
                                         uint32_t& r2, uint32_t& r3) {
    asm volatile("ldmatrix.sync.aligned.m8n8.x4.trans.shared.b16 {%0,%1,%2,%3}, [%4];"
                 : "=r"(r0), "=r"(r1), "=r"(r2), "=r"(r3) : "r"(addr));
}
__device__ __forceinline__ void mma16816(float* c, const uint32_t* a, const uint32_t* b) {
    asm volatile(
        "mma.sync.aligned.m16n8k16.row.col.f32.bf16.bf16.f32 "
        "{%0,%1,%2,%3}, {%4,%5,%6,%7}, {%8,%9}, {%0,%1,%2,%3};"
        : "+f"(c[0]), "+f"(c[1]), "+f"(c[2]), "+f"(c[3])
        : "r"(a[0]), "r"(a[1]), "r"(a[2]), "r"(a[3]), "r"(b[0]), "r"(b[1]));
}
// pack two fp32 into bf16x2 register: lo = first (col c), hi = second (col c+1)
__device__ __forceinline__ uint32_t pack_bf16x2(float lo, float hi) {
    uint32_t r; asm("cvt.rn.bf16x2.f32 %0, %1, %2;" : "=r"(r) : "f"(hi), "f"(lo));
    return r;
}

// ---------------- scratch (static device globals; no allocs) ----------------
__device__ float g_Q   [S*HID];
__device__ float g_K   [S*KVDIM];
__device__ float g_V   [S*KVDIM];
__device__ float g_attn[S*HID];
__device__ bf16 g_hH[S*HID],     g_hL[S*HID];
__device__ bf16 g_WqH[HID*HID],  g_WqL[HID*HID];
__device__ bf16 g_WkH[KVDIM*HID],g_WkL[KVDIM*HID];
__device__ bf16 g_WvH[KVDIM*HID],g_WvL[KVDIM*HID];
__device__ bf16 g_WoH[HID*HID],  g_WoL[HID*HID];
__device__ bf16 g_aH[S*HID],     g_aL[S*HID];
// bf16 splits for attention
__device__ bf16 g_Qh[S*HID],    g_Ql[S*HID];
__device__ bf16 g_bKh[S*KVDIM], g_bKl[S*KVDIM];
__device__ bf16 g_nKh[S*KVDIM], g_nKl[S*KVDIM];
__device__ bf16 g_Vh[S*KVDIM],  g_Vl[S*KVDIM];

// ---------------- fp32 -> bf16 hi/lo split ----------------
__global__ __launch_bounds__(256)
void split4_kernel(const float* __restrict__ x, bf16* __restrict__ hi,
                   bf16* __restrict__ lo, int n4)
{
    int i = blockIdx.x * 256 + threadIdx.x;
    if (i >= n4) return;
    float4 v = ((const float4*)x)[i];
    bf16 h0 = __float2bfloat16(v.x);
    bf16 h1 = __float2bfloat16(v.y);
    bf16 h2 = __float2bfloat16(v.z);
    bf16 h3 = __float2bfloat16(v.w);
    __nv_bfloat162 H0 = __nv_bfloat162(h0, h1), H1 = __nv_bfloat162(h2, h3);
    __nv_bfloat162 L0 = __nv_bfloat162(__float2bfloat16(v.x - __bfloat162float(h0)),
                                       __float2bfloat16(v.y - __bfloat162float(h1)));
    __nv_bfloat162 L1 = __nv_bfloat162(__float2bfloat16(v.z - __bfloat162float(h2)),
                                       __float2bfloat16(v.w - __bfloat162float(h3)));
    ((__nv_bfloat162*)hi)[i*2+0] = H0; ((__nv_bfloat162*)hi)[i*2+1] = H1;
    ((__nv_bfloat162*)lo)[i*2+0] = L0; ((__nv_bfloat162*)lo)[i*2+1] = L1;
}

// ---------------- mma.sync split-bf16 GEMM core ------------------------
#define STG      16384
#define SM_STAGE (4*STG)          // 64 KB
#define SM_TOTAL (2*SM_STAGE)     // 128 KB

__device__ __forceinline__ void g_load_stage(
    uint32_t sbuf,
    const bf16* __restrict__ Ah, const bf16* __restrict__ Al,
    const bf16* __restrict__ Bh, const bf16* __restrict__ Bl,
    int mBase, int nBase, int Kdim, int k0, int tid)
{
#pragma unroll
    for (int i = 0; i < 4; i++) {
        int u = i * 256 + tid;
        int r = u >> 3, c = u & 7;
        uint32_t so = (uint32_t)(r * 128 + ((c ^ (r & 7)) << 4));
        size_t eoffA = (size_t)(mBase + r) * Kdim + k0 + c * 8;
        size_t eoffB = (size_t)(nBase + r) * Kdim + k0 + c * 8;
        cp16(sbuf +          so, Ah + eoffA);
        cp16(sbuf +   STG  + so, Al + eoffA);
        cp16(sbuf + 2*STG  + so, Bh + eoffB);
        cp16(sbuf + 3*STG  + so, Bl + eoffB);
    }
}

__device__ __forceinline__ void gemm_body(
    const bf16* __restrict__ Ah, const bf16* __restrict__ Al,
    const bf16* __restrict__ Bh, const bf16* __restrict__ Bl,
    float* __restrict__ C, int Ntot, int Kdim, int mBase, int nBase, uint32_t sb)
{
    const int tid  = threadIdx.x;
    const int lane = tid & 31;
    const int wid  = tid >> 5;
    const int wm   = wid & 1;
    const int wn   = wid >> 1;

    float acc[4][4][4];
#pragma unroll
    for (int i = 0; i < 4; i++)
#pragma unroll
        for (int j = 0; j < 4; j++)
#pragma unroll
            for (int k = 0; k < 4; k++) acc[i][j][k] = 0.0f;

    const int NC = Kdim >> 6;

    g_load_stage(sb,            Ah, Al, Bh, Bl, mBase, nBase, Kdim, 0,  tid);
    CP_COMMIT();
    g_load_stage(sb + SM_STAGE, Ah, Al, Bh, Bl, mBase, nBase, Kdim, 64, tid);
    CP_COMMIT();

    const int aRow = wm * 64;
    const int bRow = wn * 32;

    for (int c = 0; c < NC; c++) {
        CP_WAIT1();
        __syncthreads();
        const uint32_t sbuf = sb + (c & 1) * SM_STAGE;
        const uint32_t sAh = sbuf, sAl = sbuf + STG, sBh = sbuf + 2*STG, sBl = sbuf + 3*STG;

#pragma unroll
        for (int ks = 0; ks < 4; ks++) {
            uint32_t aH[4][4], aL[4][4], bH[4][2], bL[4][2];
            {
                int rA = aRow + (lane & 15);
                int ccA = ks * 2 + (lane >> 4);
#pragma unroll
                for (int mf = 0; mf < 4; mf++) {
                    int r = rA + mf * 16;
                    uint32_t so = (uint32_t)(r * 128 + ((ccA ^ (r & 7)) << 4));
                    ldsm_x4(sAh + so, aH[mf][0], aH[mf][1], aH[mf][2], aH[mf][3]);
                    ldsm_x4(sAl + so, aL[mf][0], aL[mf][1], aL[mf][2], aL[mf][3]);
                }
            }
            {
                int rB0 = bRow + (lane & 7) + ((lane >> 4) << 3);
                int ccB = ks * 2 + ((lane >> 3) & 1);
#pragma unroll
                for (int nf2 = 0; nf2 < 2; nf2++) {
                    int r = rB0 + nf2 * 16;
                    uint32_t so = (uint32_t)(r * 128 + ((ccB ^ (r & 7)) << 4));
                    ldsm_x4(sBh + so, bH[nf2*2][0], bH[nf2*2][1], bH[nf2*2+1][0], bH[nf2*2+1][1]);
                    ldsm_x4(sBl + so, bL[nf2*2][0], bL[nf2*2][1], bL[nf2*2+1][0], bL[nf2*2+1][1]);
                }
            }
#pragma unroll
            for (int mf = 0; mf < 4; mf++)
#pragma unroll
                for (int nf = 0; nf < 4; nf++) {
                    mma16816(acc[mf][nf], aH[mf], bH[nf]);
                    mma16816(acc[mf][nf], aL[mf], bH[nf]);
                    mma16816(acc[mf][nf], aH[mf], bL[nf]);
                }
        }
        __syncthreads();
        if (c + 2 < NC)
            g_load_stage(sb + (c & 1) * SM_STAGE, Ah, Al, Bh, Bl,
                         mBase, nBase, Kdim, (c + 2) * 64, tid);
        CP_COMMIT();
    }

#pragma unroll
    for (int mf = 0; mf < 4; mf++) {
        int row0 = mBase + wm * 64 + mf * 16 + (lane >> 2);
#pragma unroll
        for (int nf = 0; nf < 4; nf++) {
            int col = nBase + wn * 32 + nf * 8 + (lane & 3) * 2;
            *(float2*)&C[(size_t)row0 * Ntot + col]       = make_float2(acc[mf][nf][0], acc[mf][nf][1]);
            *(float2*)&C[(size_t)(row0 + 8) * Ntot + col] = make_float2(acc[mf][nf][2], acc[mf][nf][3]);
        }
    }
}

// fused QKV projection: bx 0..15 -> Q, 16..19 -> K, 20..23 -> V
__global__ __launch_bounds__(256)
void qkv_gemm(const bf16* __restrict__ Ah, const bf16* __restrict__ Al,
              const bf16* __restrict__ WqH, const bf16* __restrict__ WqL,
              const bf16* __restrict__ WkH, const bf16* __restrict__ WkL,
              const bf16* __restrict__ WvH, const bf16* __restrict__ WvL,
              float* __restrict__ Cq, float* __restrict__ Ck, float* __restrict__ Cv)
{
    extern __shared__ char dyns[];
    uint32_t sb = smem_u32(dyns);
    int bx = blockIdx.x, mBase = blockIdx.y * 128;
    if (bx < 16)      gemm_body(Ah, Al, WqH, WqL, Cq, HID,   HID, mBase, bx*128,      sb);
    else if (bx < 20) gemm_body(Ah, Al, WkH, WkL, Ck, KVDIM, HID, mBase, (bx-16)*128, sb);
    else              gemm_body(Ah, Al, WvH, WvL, Cv, KVDIM, HID, mBase, (bx-20)*128, sb);
}

__global__ __launch_bounds__(256)
void wo_gemm(const bf16* __restrict__ Ah, const bf16* __restrict__ Al,
             const bf16* __restrict__ Bh, const bf16* __restrict__ Bl,
             float* __restrict__ C)
{
    extern __shared__ char dyns[];
    uint32_t sb = smem_u32(dyns);
    gemm_body(Ah, Al, Bh, Bl, C, HID, HID, blockIdx.y*128, blockIdx.x*128, sb);
}

// ---------------- RoPE + split: Q (per-row variant, scaled), bK/nK, V ------
__device__ __forceinline__ void split_w(bf16* hp, bf16* lp, float x) {
    bf16 h = __float2bfloat16(x);
    *hp = h;
    *lp = __float2bfloat16(x - __bfloat162float(h));
}

__global__ void rope_split_kernel(const float* __restrict__ Q, const float* __restrict__ K,
                                  const float* __restrict__ V,
                                  bf16* __restrict__ qh, bf16* __restrict__ ql,
                                  bf16* __restrict__ kbh, bf16* __restrict__ kbl,
                                  bf16* __restrict__ knh, bf16* __restrict__ knl,
                                  bf16* __restrict__ vh, bf16* __restrict__ vl)
{
    const int s = blockIdx.x;
    const int tid = threadIdx.x; // 256
    const bool narrowRow = (s >= CTX);
    const float QS = 1.4426950408889634f * 0.125f;   // log2(e)/sqrt(64)

    __shared__ float cb[32], sb[32], cn[32], sn[32];
    if (tid < 32) {
        double inv = pow(10000.0, -(double)tid / 32.0);
        double ab = (double)s * inv;
        double an = ((double)s * 0.25) * inv;
        cb[tid] = (float)cos(ab); sb[tid] = (float)sin(ab);
        cn[tid] = (float)cos(an); sn[tid] = (float)sin(an);
    }
    __syncthreads();

    for (int p = tid; p < NH * 32; p += 256) {
        int h = p >> 5, d = p & 31;
        size_t base = (size_t)s * HID + h * HD;
        float x1 = Q[base + d];
        float x2 = Q[base + d + 32];
        float c  = narrowRow ? cn[d] : cb[d];
        float si = narrowRow ? sn[d] : sb[d];
        split_w(qh + base + d,      ql + base + d,      (x1 * c - x2 * si) * QS);
        split_w(qh + base + d + 32, ql + base + d + 32, (x2 * c + x1 * si) * QS);
    }
    for (int p = tid; p < NKV * 32; p += 256) {
        int h = p >> 5, d = p & 31;
        size_t base = (size_t)s * KVDIM + h * HD;
        float x1 = K[base + d];
        float x2 = K[base + d + 32];
        split_w(kbh + base + d,      kbl + base + d,      x1 * cb[d] - x2 * sb[d]);
        split_w(kbh + base + d + 32, kbl + base + d + 32, x2 * cb[d] + x1 * sb[d]);
        split_w(knh + base + d,      knl + base + d,      x1 * cn[d] - x2 * sn[d]);
        split_w(knh + base + d + 32, knl + base + d + 32, x2 * cn[d] + x1 * sn[d]);
    }
    for (int e = tid; e < KVDIM; e += 256) {
        size_t base = (size_t)s * KVDIM + e;
        split_w(vh + base, vl + base, V[base]);
    }
}

// ---------------- Tensor-core flash attention -------------------------------
// CTA: 64 q-rows x 1 head. 4 warps x 16 rows. Bc=64 key tiles, double-buffered.
// DUAL: last q-tile computes both rope variants' scores and selects per row.

template<bool DUAL>
__device__ __forceinline__ void fa_load_stage(
    uint32_t sb, int kt, int kvh, int tid,
    const bf16* __restrict__ Kbh, const bf16* __restrict__ Kbl,
    const bf16* __restrict__ Knh, const bf16* __restrict__ Knl,
    const bf16* __restrict__ Vh, const bf16* __restrict__ Vl)
{
#pragma unroll
    for (int i = 0; i < 4; i++) {
        int u = i * 128 + tid;      // 0..511
        int r = u >> 3, c = u & 7;
        uint32_t so = (uint32_t)(r * 128 + ((c ^ (r & 7)) << 4));
        size_t go = (size_t)(kt * 64 + r) * KVDIM + kvh * 64 + c * 8;
        cp16(sb +         so, Kbh + go);
        cp16(sb + 8192  + so, Kbl + go);
        cp16(sb + 16384 + so, Vh + go);
        cp16(sb + 24576 + so, Vl + go);
        if (DUAL) {
            cp16(sb + 32768 + so, Knh + go);
            cp16(sb + 40960 + so, Knl + go);
        }
    }
}

__device__ __forceinline__ void fa_compute_S(
    float s[8][4], uint32_t sKh, uint32_t sKl,
    const uint32_t qfh[4][4], const uint32_t qfl[4][4], int lane)
{
#pragma unroll
    for (int kk = 0; kk < 4; kk++) {
        uint32_t kh[8][2], kl[8][2];
        int rB0 = (lane & 7) + ((lane >> 4) << 3);
        int ccB = kk * 2 + ((lane >> 3) & 1);
#pragma unroll
        for (int nb = 0; nb < 4; nb++) {
            int r = nb * 16 + rB0;
            uint32_t so = (uint32_t)(r * 128 + ((ccB ^ (r & 7)) << 4));
            ldsm_x4(sKh + so, kh[nb*2][0], kh[nb*2][1], kh[nb*2+1][0], kh[nb*2+1][1]);
            ldsm_x4(sKl + so, kl[nb*2][0], kl[nb*2][1], kl[nb*2+1][0], kl[nb*2+1][1]);
        }
#pragma unroll
        for (int nf = 0; nf < 8; nf++) {
            mma16816(s[nf], qfh[kk], kh[nf]);
            mma16816(s[nf], qfl[kk], kh[nf]);
            mma16816(s[nf], qfh[kk], kl[nf]);
        }
    }
}

template<bool DUAL>
__global__ __launch_bounds__(128, DUAL ? 1 : 2)
void flash_mma(const bf16* __restrict__ Qh, const bf16* __restrict__ Ql,
               const bf16* __restrict__ Kbh, const bf16* __restrict__ Kbl,
               const bf16* __restrict__ Knh, const bf16* __restrict__ Knl,
               const bf16* __restrict__ Vh,  const bf16* __restrict__ Vl,
               float* __restrict__ attnOut)
{
    constexpr int STAGE = DUAL ? 49152 : 32768;
    extern __shared__ char dyn[];
    const uint32_t sQ = smem_u32(dyn);           // Qh 8K | Ql 8K | stage0 | stage1

    const int tid = threadIdx.x, lane = tid & 31, w = tid >> 5;
    const int qt = DUAL ? (S/64 - 1) : (S/64 - 2 - (int)blockIdx.x);   // heavy first
    const int h = blockIdx.y, kvh = h >> 2;

    // ---- Q tile load (hi+lo) ----
    {
        const bf16* gQh = Qh + (size_t)(qt * 64) * HID + h * 64;
        const bf16* gQl = Ql + (size_t)(qt * 64) * HID + h * 64;
#pragma unroll
        for (int i = 0; i < 4; i++) {
            int u = i * 128 + tid;
            int r = u >> 3, c = u & 7;
            uint32_t so = (uint32_t)(r * 128 + ((c ^ (r & 7)) << 4));
            cp16(sQ +        so, gQh + (size_t)r * HID + c * 8);
            cp16(sQ + 8192 + so, gQl + (size_t)r * HID + c * 8);
        }
    }
    fa_load_stage<DUAL>(sQ + 16384, 0, kvh, tid, Kbh, Kbl, Knh, Knl, Vh, Vl);
    CP_COMMIT();
    if (qt >= 1)
        fa_load_stage<DUAL>(sQ + 16384 + STAGE, 1, kvh, tid, Kbh, Kbl, Knh, Knl, Vh, Vl);
    CP_COMMIT();

    CP_WAIT1();
    __syncthreads();

    // ---- Q fragments (kept in registers for all tiles) ----
    uint32_t qfh[4][4], qfl[4][4];
    {
        int rA = w * 16 + (lane & 15);
#pragma unroll
        for (int kk = 0; kk < 4; kk++) {
            int cc = kk * 2 + (lane >> 4);
            uint32_t so = (uint32_t)(rA * 128 + ((cc ^ (rA & 7)) << 4));
            ldsm_x4(sQ + so,        qfh[kk][0], qfh[kk][1], qfh[kk][2], qfh[kk][3]);
            ldsm_x4(sQ + 8192 + so, qfl[kk][0], qfl[kk][1], qfl[kk][2], qfl[kk][3]);
        }
    }

    float o[8][4];
#pragma unroll
    for (int nf = 0; nf < 8; nf++)
#pragma unroll
        for (int j = 0; j < 4; j++) o[nf][j] = 0.0f;
    float m0 = -1e30f, m1 = -1e30f, l0 = 0.0f, l1 = 0.0f;

    const int rg0 = qt * 64 + w * 16 + (lane >> 2);
    const int rg1 = rg0 + 8;

    for (int kt = 0; kt <= qt; kt++) {
        if (kt) { CP_WAIT1(); __syncthreads(); }
        const uint32_t sb = sQ + 16384 + (kt & 1) * STAGE;

        // ---- S = Q K^T ----
        float s[8][4];
#pragma unroll
        for (int nf = 0; nf < 8; nf++)
#pragma unroll
            for (int j = 0; j < 4; j++) s[nf][j] = 0.0f;
        fa_compute_S(s, sb, sb + 8192, qfh, qfl, lane);

        if (DUAL) {
            float sn[8][4];
#pragma unroll
            for (int nf = 0; nf < 8; nf++)
#pragma unroll
                for (int j = 0; j < 4; j++) sn[nf][j] = 0.0f;
            fa_compute_S(sn, sb + 32768, sb + 40960, qfh, qfl, lane);
            if (rg0 >= CTX) {
#pragma unroll
                for (int nf = 0; nf < 8; nf++) { s[nf][0] = sn[nf][0]; s[nf][1] = sn[nf][1]; }
            }
            if (rg1 >= CTX) {
#pragma unroll
                for (int nf = 0; nf < 8; nf++) { s[nf][2] = sn[nf][2]; s[nf][3] = sn[nf][3]; }
            }
        }

        // ---- causal mask (diagonal tile only) ----
        if (kt == qt) {
#pragma unroll
            for (int nf = 0; nf < 8; nf++) {
                int c0 = kt * 64 + nf * 8 + (lane & 3) * 2;
                if (c0     > rg0) s[nf][0] = -1e30f;
                if (c0 + 1 > rg0) s[nf][1] = -1e30f;
                if (c0     > rg1) s[nf][2] = -1e30f;
                if (c0 + 1 > rg1) s[nf][3] = -1e30f;
            }
        }

        // ---- online softmax (base-2; scale folded into Q) ----
        float mr0 = -1e30f, mr1 = -1e30f;
#pragma unroll
        for (int nf = 0; nf < 8; nf++) {
            mr0 = fmaxf(mr0, fmaxf(s[nf][0], s[nf][1]));
            mr1 = fmaxf(mr1, fmaxf(s[nf][2], s[nf][3]));
        }
        mr0 = fmaxf(mr0, __shfl_xor_sync(0xffffffffu, mr0, 1));
        mr0 = fmaxf(mr0, __shfl_xor_sync(0xffffffffu, mr0, 2));
        mr1 = fmaxf(mr1, __shfl_xor_sync(0xffffffffu, mr1, 1));
        mr1 = fmaxf(mr1, __shfl_xor_sync(0xffffffffu, mr1, 2));

        float mn0 = fmaxf(m0, mr0), mn1 = fmaxf(m1, mr1);
        float sc0 = exp2f(m0 - mn0), sc1 = exp2f(m1 - mn1);
        m0 = mn0; m1 = mn1;
        l0 *= sc0; l1 *= sc1;
#pragma unroll
        for (int nf = 0; nf < 8; nf++) {
            o[nf][0] *= sc0; o[nf][1] *= sc0;
            o[nf][2] *= sc1; o[nf][3] *= sc1;
        }

        uint32_t pH[4][4], pL[4][4];
        float sum0 = 0.0f, sum1 = 0.0f;
#pragma unroll
        for (int nf = 0; nf < 8; nf++) {
            float p0 = exp2f(s[nf][0] - m0), p1 = exp2f(s[nf][1] - m0);
            float p2 = exp2f(s[nf][2] - m1), p3 = exp2f(s[nf][3] - m1);
            sum0 += p0 + p1; sum1 += p2 + p3;
            float r0 = __bfloat162float(__float2bfloat16(p0));
            float r1 = __bfloat162float(__float2bfloat16(p1));
            float r2 = __bfloat162float(__float2bfloat16(p2));
            float r3 = __bfloat162float(__float2bfloat16(p3));
            int kk = nf >> 1;
            int off = (nf & 1) * 2;
            pH[kk][off + 0] = pack_bf16x2(p0, p1);
            pH[kk][off + 1] = pack_bf16x2(p2, p3);
            pL[kk][off + 0] = pack_bf16x2(p0 - r0, p1 - r1);
            pL[kk][off + 1] = pack_bf16x2(p2 - r2, p3 - r3);
        }
        sum0 += __shfl_xor_sync(0xffffffffu, sum0, 1);
        sum0 += __shfl_xor_sync(0xffffffffu, sum0, 2);
        sum1 += __shfl_xor_sync(0xffffffffu, sum1, 1);
        sum1 += __shfl_xor_sync(0xffffffffu, sum1, 2);
        l0 += sum0; l1 += sum1;

        // ---- O += P V ----
        const uint32_t sVh = sb + 16384, sVl = sb + 24576;
#pragma unroll
        for (int kk = 0; kk < 4; kk++) {
            uint32_t vh[8][2], vl[8][2];
            int key0 = kk * 16 + (lane & 7) + ((lane >> 3) & 1) * 8;
#pragma unroll
            for (int nb = 0; nb < 4; nb++) {
                int chunk = nb * 2 + (lane >> 4);
                uint32_t so = (uint32_t)(key0 * 128 + ((chunk ^ (key0 & 7)) << 4));
                ldsm_x4t(sVh + so, vh[nb*2][0], vh[nb*2][1], vh[nb*2+1][0], vh[nb*2+1][1]);
                ldsm_x4t(sVl + so, vl[nb*2][0], vl[nb*2][1], vl[nb*2+1][0], vl[nb*2+1][1]);
            }
#pragma unroll
            for (int nf = 0; nf < 8; nf++) {
                mma16816(o[nf], pH[kk], vh[nf]);
                mma16816(o[nf], pL[kk], vh[nf]);
                mma16816(o[nf], pH[kk], vl[nf]);
            }
        }

        __syncthreads();
        if (kt + 2 <= qt)
            fa_load_stage<DUAL>(sQ + 16384 + (kt & 1) * STAGE, kt + 2, kvh, tid,
                                Kbh, Kbl, Knh, Knl, Vh, Vl);
        CP_COMMIT();
    }

    float inv0 = 1.0f / l0, inv1 = 1.0f / l1;
#pragma unroll
    for (int nf = 0; nf < 8; nf++) {
        int col = h * 64 + nf * 8 + (lane & 3) * 2;
        *(float2*)&attnOut[(size_t)rg0 * HID + col] = make_float2(o[nf][0]*inv0, o[nf][1]*inv0);
        *(float2*)&attnOut[(size_t)rg1 * HID + col] = make_float2(o[nf][2]*inv1, o[nf][3]*inv1);
    }
}

// ---------------- launch ----------------
extern "C" void kernel_launch(void* const* d_in, const int* in_sizes, int n_in,
                              void* d_out, int out_size)
{
    const float* hidden = (const float*)d_in[0];
    const float* Wq = (const float*)d_in[3];
    const float* Wk = (const float*)d_in[4];
    const float* Wv = (const float*)d_in[5];
    const float* Wo = (const float*)d_in[6];
    float* out = (float*)d_out;

    float *qB, *kB, *vB, *atB;
    cudaGetSymbolAddress((void**)&qB,  g_Q);
    cudaGetSymbolAddress((void**)&kB,  g_K);
    cudaGetSymbolAddress((void**)&vB,  g_V);
    cudaGetSymbolAddress((void**)&atB, g_attn);

    bf16 *hH,*hL,*WqH,*WqL,*WkH,*WkL,*WvH,*WvL,*WoH,*WoL,*aH,*aL;
    cudaGetSymbolAddress((void**)&hH,  g_hH);  cudaGetSymbolAddress((void**)&hL,  g_hL);
    cudaGetSymbolAddress((void**)&WqH, g_WqH); cudaGetSymbolAddress((void**)&WqL, g_WqL);
    cudaGetSymbolAddress((void**)&WkH, g_WkH); cudaGetSymbolAddress((void**)&WkL, g_WkL);
    cudaGetSymbolAddress((void**)&WvH, g_WvH); cudaGetSymbolAddress((void**)&WvL, g_WvL);
    cudaGetSymbolAddress((void**)&WoH, g_WoH); cudaGetSymbolAddress((void**)&WoL, g_WoL);
    cudaGetSymbolAddress((void**)&aH,  g_aH);  cudaGetSymbolAddress((void**)&aL,  g_aL);

    bf16 *Qh,*Ql,*bKh,*bKl,*nKh,*nKl,*Vh,*Vl;
    cudaGetSymbolAddress((void**)&Qh,  g_Qh);  cudaGetSymbolAddress((void**)&Ql,  g_Ql);
    cudaGetSymbolAddress((void**)&bKh, g_bKh); cudaGetSymbolAddress((void**)&bKl, g_bKl);
    cudaGetSymbolAddress((void**)&nKh, g_nKh); cudaGetSymbolAddress((void**)&nKl, g_nKl);
    cudaGetSymbolAddress((void**)&Vh,  g_Vh);  cudaGetSymbolAddress((void**)&Vl,  g_Vl);

    cudaFuncSetAttribute(qkv_gemm, cudaFuncAttributeMaxDynamicSharedMemorySize, SM_TOTAL);
    cudaFuncSetAttribute(wo_gemm,  cudaFuncAttributeMaxDynamicSharedMemorySize, SM_TOTAL);
    const int FA_SMEM_N = 16384 + 2*32768;   // 81920
    const int FA_SMEM_D = 16384 + 2*49152;   // 114688
    cudaFuncSetAttribute(flash_mma<false>, cudaFuncAttributeMaxDynamicSharedMemorySize, FA_SMEM_N);
    cudaFuncSetAttribute(flash_mma<true>,  cudaFuncAttributeMaxDynamicSharedMemorySize, FA_SMEM_D);

    split4_kernel<<<(S*HID/4 + 255)/256, 256>>>(hidden, hH, hL, S*HID/4);
    split4_kernel<<<(HID*HID/4 + 255)/256, 256>>>(Wq, WqH, WqL, HID*HID/4);
    split4_kernel<<<(KVDIM*HID/4 + 255)/256, 256>>>(Wk, WkH, WkL, KVDIM*HID/4);
    split4_kernel<<<(KVDIM*HID/4 + 255)/256, 256>>>(Wv, WvH, WvL, KVDIM*HID/4);
    split4_kernel<<<(HID*HID/4 + 255)/256, 256>>>(Wo, WoH, WoL, HID*HID/4);

    qkv_gemm<<<dim3(24, 16), 256, SM_TOTAL>>>(hH, hL, WqH, WqL, WkH, WkL, WvH, WvL,
                                              qB, kB, vB);

    rope_split_kernel<<<S, 256>>>(qB, kB, vB, Qh, Ql, bKh, bKl, nKh, nKl, Vh, Vl);

    // boundary tile (rows 1984..2047, contains CTX) — dual-variant kernel
    flash_mma<true><<<dim3(1, NH), 128, FA_SMEM_D>>>(Qh, Ql, bKh, bKl, nKh, nKl, Vh, Vl, atB);
    // remaining tiles, heavy first
    flash_mma<false><<<dim3(S/64 - 1, NH), 128, FA_SMEM_N>>>(Qh, Ql, bKh, bKl, nKh, nKl, Vh, Vl, atB);

    split4_kernel<<<(S*HID/4 + 255)/256, 256>>>(atB, aH, aL, S*HID/4);
    wo_gemm<<<dim3(16, 16), 256, SM_TOTAL>>>(aH, aL, WoH, WoL, out);
}